// round 15
// baseline (speedup 1.0000x reference)
#include <cuda_runtime.h>
#include <cuda_bf16.h>
#include <cuda_fp16.h>
#include <math.h>
#include <stdint.h>

// ---------------- constants ----------------
constexpr int E_  = 16;
constexpr int T_  = 512;
constexpr int BT  = 1024;   // B*T
constexpr float EPS_ = 1e-8f;
constexpr float LO_SCALE   = 2048.f;            // 2^11
constexpr float LO_UNSCALE = 4.8828125e-4f;     // 2^-11

// ---------------- f32 scratch ----------------
__device__ float g_P    [BT * 2048];
__device__ float g_XI   [BT * 2048];
__device__ float g_XR   [BT * 1024];
__device__ float g_glcm [BT * 1024];
__device__ float g_delta[BT * 1024];
__device__ float g_Bmat [BT * 16384];
__device__ float g_Cmat [BT * 16384];
__device__ float g_y    [BT * 1024];
__device__ float g_yo   [BT * 1024];
__device__ float g_g1   [BT * 1024];
__device__ float g_g2   [BT * 1024];
__device__ float g_h    [BT * 1024];
__device__ float g_e2   [2 * BT * 1024];
__device__ int   g_cnt  [E_];
__device__ int   g_list [E_ * 2048];
__device__ float g_w    [2 * BT];

// ---------------- fp16 MoE intermediate ----------------
__device__ __half g_e1h [2 * BT * 4096];

// ---------------- fp16 hi / scaled-lo activation mirrors (dense path) ----------
__device__ __half g_xh [BT * 1024], g_xl [BT * 1024];
__device__ __half g_XIh[BT * 2048], g_XIl[BT * 2048];
__device__ __half g_yh [BT * 1024], g_yl [BT * 1024];

// ---------------- helpers ----------------
__device__ __forceinline__ float sigmoidf_(float x) { return 1.f / (1.f + expf(-x)); }

__device__ __forceinline__ float block_sum256(float v) {
    __shared__ float sh[8];
    int lane = threadIdx.x & 31, w = threadIdx.x >> 5;
    __syncthreads();
#pragma unroll
    for (int o = 16; o; o >>= 1) v += __shfl_xor_sync(0xffffffffu, v, o);
    if (lane == 0) sh[w] = v;
    __syncthreads();
    float s = 0.f;
#pragma unroll
    for (int i = 0; i < 8; i++) s += sh[i];
    return s;
}

__device__ __forceinline__ uint32_t smem_u32(const void* p) {
    return (uint32_t)__cvta_generic_to_shared(p);
}

__device__ __forceinline__ void ldsm_x4(uint32_t& r0, uint32_t& r1, uint32_t& r2, uint32_t& r3, uint32_t addr) {
    asm volatile("ldmatrix.sync.aligned.m8n8.x4.shared.b16 {%0,%1,%2,%3}, [%4];"
        : "=r"(r0), "=r"(r1), "=r"(r2), "=r"(r3) : "r"(addr));
}
__device__ __forceinline__ void ldsm_x4_t(uint32_t& r0, uint32_t& r1, uint32_t& r2, uint32_t& r3, uint32_t addr) {
    asm volatile("ldmatrix.sync.aligned.m8n8.x4.trans.shared.b16 {%0,%1,%2,%3}, [%4];"
        : "=r"(r0), "=r"(r1), "=r"(r2), "=r"(r3) : "r"(addr));
}
// fp16 x fp16 -> f32 accum
__device__ __forceinline__ void mma_f16(float* c, const uint32_t* a, const uint32_t* b) {
    asm volatile("mma.sync.aligned.m16n8k16.row.col.f32.f16.f16.f32 "
        "{%0,%1,%2,%3}, {%4,%5,%6,%7}, {%8,%9}, {%0,%1,%2,%3};"
        : "+f"(c[0]), "+f"(c[1]), "+f"(c[2]), "+f"(c[3])
        : "r"(a[0]), "r"(a[1]), "r"(a[2]), "r"(a[3]), "r"(b[0]), "r"(b[1]));
}
// fp16 x fp16 -> f16 accum (correction passes)
__device__ __forceinline__ void mma_f16h(uint32_t* c, const uint32_t* a, const uint32_t* b) {
    asm volatile("mma.sync.aligned.m16n8k16.row.col.f16.f16.f16.f16 "
        "{%0,%1}, {%2,%3,%4,%5}, {%6,%7}, {%0,%1};"
        : "+r"(c[0]), "+r"(c[1])
        : "r"(a[0]), "r"(a[1]), "r"(a[2]), "r"(a[3]), "r"(b[0]), "r"(b[1]));
}

__device__ __forceinline__ uint32_t packh(__half a, __half b) {
    return ((uint32_t)__half_as_ushort(b) << 16) | __half_as_ushort(a);
}
// 16 f32 -> fp16 hi words + scaled-lo words
__device__ __forceinline__ void cvt_sh16(const float* v, uint32_t* hi, uint32_t* lo) {
#pragma unroll
    for (int i = 0; i < 8; i++) {
        float x0 = v[2 * i], x1 = v[2 * i + 1];
        __half h0 = __float2half_rn(x0), h1 = __float2half_rn(x1);
        __half l0 = __float2half_rn((x0 - __half2float(h0)) * LO_SCALE);
        __half l1 = __float2half_rn((x1 - __half2float(h1)) * LO_SCALE);
        hi[i] = packh(h0, h1);
        lo[i] = packh(l0, l1);
    }
}
// plain fp16 (MoE single-pass)
__device__ __forceinline__ void cvt_h16(const float* v, uint32_t* h) {
#pragma unroll
    for (int i = 0; i < 8; i++) {
        __half2 p = __floats2half2_rn(v[2 * i], v[2 * i + 1]);
        h[i] = *(uint32_t*)&p;
    }
}

__device__ __forceinline__ void cp16(uint32_t dst, const void* src) {
    asm volatile("cp.async.cg.shared.global [%0], [%1], 16;" :: "r"(dst), "l"(src));
}
#define CP_COMMIT() asm volatile("cp.async.commit_group;" ::: "memory")
#define CP_WAIT1()  asm volatile("cp.async.wait_group 1;" ::: "memory")

// ============================================================================
// Dense GEMM, 3-way z-merged, fp16 hi/scaled-lo split:
//   pass1: Ah·Bh (f32 accum); pass2/3: Ah·Bl + Al·Bh (f16 accum, ×2^-11 at end)
// ============================================================================
constexpr int AP = 10240;
constexpr int BP = 8704;
constexpr int STG = 2 * AP + 2 * BP;
constexpr int DSMEM = 2 * STG;

__global__ __launch_bounds__(256)
void wgemm3(const __half* __restrict__ A0h, const __half* __restrict__ A0l,
            const __half* __restrict__ A1h, const __half* __restrict__ A1l,
            const __half* __restrict__ A2h, const __half* __restrict__ A2l,
            const float* __restrict__ W0, const float* __restrict__ W1, const float* __restrict__ W2,
            const float* __restrict__ b0, const float* __restrict__ b1, const float* __restrict__ b2,
            float* __restrict__ C0, float* __restrict__ C1, float* __restrict__ C2,
            int N0, int N1, int N2, int e0, int e1, int e2,
            __half* __restrict__ Ch, __half* __restrict__ Cl,
            int K) {
    extern __shared__ char smem[];
    const uint32_t sb = smem_u32(smem);

    const int z = blockIdx.z;
    const __half* __restrict__ Ah = (z == 0) ? A0h : (z == 1) ? A1h : A2h;
    const __half* __restrict__ Al = (z == 0) ? A0l : (z == 1) ? A1l : A2l;
    const float* __restrict__ W    = (z == 0) ? W0 : (z == 1) ? W1 : W2;
    const float* __restrict__ bias = (z == 0) ? b0 : (z == 1) ? b1 : b2;
    float* __restrict__ C          = (z == 0) ? C0 : (z == 1) ? C1 : C2;
    const int Ntot = (z == 0) ? N0 : (z == 1) ? N1 : N2;
    const int EPI  = (z == 0) ? e0 : (z == 1) ? e1 : e2;
    const bool bout = (Ch != nullptr) && (z == 1);

    const int nBase = blockIdx.y * 128;
    if (nBase >= Ntot) return;

    const int tid = threadIdx.x;
    const int warp = tid >> 5, lane = tid & 31;
    const int wm = warp & 1, wn = warp >> 1;
    const int mBase = blockIdx.x * 128;
    const int wmBase = wm * 64, wnBase = wn * 32;

    const int S = K >> 5;

    auto load_A = [&](int s, int b) {
        const int k0 = s << 5;
        const uint32_t base = sb + b * STG;
#pragma unroll
        for (int i = 0; i < 2; i++) {
            int c = i * 256 + tid;
            int r = c >> 2, c4 = c & 3;
            uint32_t dst = base + (uint32_t)(r * 80 + c4 * 16);
            cp16(dst,      Ah + (size_t)(mBase + r) * K + k0 + c4 * 8);
            cp16(dst + AP, Al + (size_t)(mBase + r) * K + k0 + c4 * 8);
        }
    };

    const int wr = tid >> 3, wc = (tid & 7) * 16;
    float wreg[16];
    auto ldg_W = [&](int s) {
        const float* src = W + (size_t)((s << 5) + wr) * Ntot + nBase + wc;
        *(float4*)&wreg[0]  = *(const float4*)(src);
        *(float4*)&wreg[4]  = *(const float4*)(src + 4);
        *(float4*)&wreg[8]  = *(const float4*)(src + 8);
        *(float4*)&wreg[12] = *(const float4*)(src + 12);
    };
    auto sts_W = [&](int b) {
        uint32_t hi[8], lo[8];
        cvt_sh16(wreg, hi, lo);
        const uint32_t off = b * STG + 2 * AP + (uint32_t)(wr * 272 + wc * 2);
        *(uint4*)(smem + off)           = *(uint4*)&hi[0];
        *(uint4*)(smem + off + 16)      = *(uint4*)&hi[4];
        *(uint4*)(smem + off + BP)      = *(uint4*)&lo[0];
        *(uint4*)(smem + off + BP + 16) = *(uint4*)&lo[4];
    };

    float acc[4][4][4] = {};
    uint32_t acc16[4][4][2] = {};   // f16x2 correction accumulators

    const int lrow = lane & 15;
    const int lcolB = ((lane >> 4) << 3) * 2;

    ldg_W(0);
    load_A(0, 0); CP_COMMIT();
    load_A(1, 1); CP_COMMIT();

    for (int s = 0; s < S; s++) {
        const int b = s & 1;
        sts_W(b);
        if (s + 1 < S) ldg_W(s + 1);
        CP_WAIT1();
        __syncthreads();

        const uint32_t base = sb + b * STG;
        const uint32_t aH = base + (uint32_t)((wmBase + lrow) * 80) + lcolB;
        const uint32_t aL = aH + AP;
        const uint32_t bH = base + 2 * AP + (uint32_t)(lrow * 272) + (uint32_t)(wnBase * 2) + lcolB;
        const uint32_t bL = bH + BP;

#pragma unroll
        for (int chunk = 0; chunk < 2; chunk++) {
            uint32_t Afh[4][4], Afl[4][4], Bfh[4][2], Bfl[4][2];
#pragma unroll
            for (int mi = 0; mi < 4; mi++) {
                ldsm_x4(Afh[mi][0], Afh[mi][1], Afh[mi][2], Afh[mi][3],
                        aH + mi * (16 * 80) + chunk * 32);
                ldsm_x4(Afl[mi][0], Afl[mi][1], Afl[mi][2], Afl[mi][3],
                        aL + mi * (16 * 80) + chunk * 32);
            }
#pragma unroll
            for (int g = 0; g < 2; g++) {
                uint32_t r0, r1, r2, r3;
                ldsm_x4_t(r0, r1, r2, r3, bH + chunk * (16 * 272) + g * 32);
                Bfh[2 * g][0] = r0; Bfh[2 * g][1] = r1; Bfh[2 * g + 1][0] = r2; Bfh[2 * g + 1][1] = r3;
                ldsm_x4_t(r0, r1, r2, r3, bL + chunk * (16 * 272) + g * 32);
                Bfl[2 * g][0] = r0; Bfl[2 * g][1] = r1; Bfl[2 * g + 1][0] = r2; Bfl[2 * g + 1][1] = r3;
            }
#pragma unroll
            for (int mi = 0; mi < 4; mi++)
#pragma unroll
                for (int ni = 0; ni < 4; ni++) {
                    mma_f16 (acc[mi][ni],   Afh[mi], Bfh[ni]);
                    mma_f16h(acc16[mi][ni], Afh[mi], Bfl[ni]);
                    mma_f16h(acc16[mi][ni], Afl[mi], Bfh[ni]);
                }
        }
        __syncthreads();
        if (s + 2 < S) load_A(s + 2, b);
        CP_COMMIT();
    }

    const int lr = lane >> 2, lc = (lane & 3) * 2;
#pragma unroll
    for (int mi = 0; mi < 4; mi++) {
        size_t row0 = (size_t)(mBase + wmBase + mi * 16 + lr);
#pragma unroll
        for (int ni = 0; ni < 4; ni++) {
            int col = nBase + wnBase + ni * 8 + lc;
            float bb0 = bias[col], bb1 = bias[col + 1];
            __half2 p0 = *(__half2*)&acc16[mi][ni][0];  // (c0, c1): row lr
            __half2 p1 = *(__half2*)&acc16[mi][ni][1];  // (c2, c3): row lr+8
            float v[4] = {acc[mi][ni][0] + LO_UNSCALE * __half2float(p0.x) + bb0,
                          acc[mi][ni][1] + LO_UNSCALE * __half2float(p0.y) + bb1,
                          acc[mi][ni][2] + LO_UNSCALE * __half2float(p1.x) + bb0,
                          acc[mi][ni][3] + LO_UNSCALE * __half2float(p1.y) + bb1};
            if (EPI == 1) {
#pragma unroll
                for (int q = 0; q < 4; q++)
                    v[q] = fmaxf(v[q], 0.f) + log1pf(expf(-fabsf(v[q])));
            } else if (EPI == 2) {
#pragma unroll
                for (int q = 0; q < 4; q++) v[q] = sigmoidf_(v[q]);
            }
            size_t i0 = row0 * Ntot + col;
            size_t i1 = (row0 + 8) * Ntot + col;
            *(float2*)(C + i0) = make_float2(v[0], v[1]);
            *(float2*)(C + i1) = make_float2(v[2], v[3]);
            if (bout) {
                __half h0 = __float2half_rn(v[0]), h1 = __float2half_rn(v[1]);
                __half h2 = __float2half_rn(v[2]), h3 = __float2half_rn(v[3]);
                Ch[i0] = h0; Ch[i0 + 1] = h1; Ch[i1] = h2; Ch[i1 + 1] = h3;
                Cl[i0]     = __float2half_rn((v[0] - __half2float(h0)) * LO_SCALE);
                Cl[i0 + 1] = __float2half_rn((v[1] - __half2float(h1)) * LO_SCALE);
                Cl[i1]     = __float2half_rn((v[2] - __half2float(h2)) * LO_SCALE);
                Cl[i1 + 1] = __float2half_rn((v[3] - __half2float(h3)) * LO_SCALE);
            }
        }
    }
}

// ============================================================================
// MoE gather-GEMM, single-pass fp16 (verified R12)
// ============================================================================
constexpr int MA_STR = 40;
constexpr int MB_STR = 136;

template <int PHASE>
__global__ __launch_bounds__(256)
void moe_fp16_kernel(const float* __restrict__ Wall, const float* __restrict__ ball) {
    constexpr int K = (PHASE == 1) ? 1024 : 4096;
    constexpr int N = (PHASE == 1) ? 4096 : 1024;
    const int e = blockIdx.z;
    const int mc = g_cnt[e];
    const int m0 = blockIdx.x * 128;
    if (m0 >= mc) return;
    const float* W = Wall + (size_t)e * K * N;
    const float* bias = ball + (size_t)e * N;

    __shared__ int rows[128];
    __shared__ __half sA[128][MA_STR];
    __shared__ __half sB[32][MB_STR];

    const int tid = threadIdx.x;
    const int warp = tid >> 5, lane = tid & 31;
    const int wm = warp & 1, wn = warp >> 1;
    const int nBase = blockIdx.y * 128;
    const int wmBase = wm * 64, wnBase = wn * 32;

    if (tid < 128) {
        int m = m0 + tid;
        rows[tid] = (m < mc) ? g_list[e * 2048 + m] : -1;
    }
    __syncthreads();

    const int arow = tid >> 1, acb = (tid & 1) * 16;
    const int brow = tid >> 3, bcb = (tid & 7) * 16;
    const int arid = rows[arow];

    const int lrow = lane & 15;
    const int lcol = (lane >> 4) << 3;
    const uint32_t aBase = smem_u32(&sA[wmBase + lrow][lcol]);
    const uint32_t bBase = smem_u32(&sB[lrow][wnBase + lcol]);

    float acc[4][4][4] = {};

    for (int k0 = 0; k0 < K; k0 += 32) {
        if (PHASE == 1) {
            float av[16];
            if (arid >= 0) {
                const float* ap = g_h + (size_t)(arid >> 1) * 1024 + k0 + acb;
                *(float4*)&av[0]  = *(const float4*)(ap);
                *(float4*)&av[4]  = *(const float4*)(ap + 4);
                *(float4*)&av[8]  = *(const float4*)(ap + 8);
                *(float4*)&av[12] = *(const float4*)(ap + 12);
            } else {
#pragma unroll
                for (int i = 0; i < 16; i++) av[i] = 0.f;
            }
            uint32_t hw[8];
            cvt_h16(av, hw);
            *(uint4*)&sA[arow][acb]     = *(uint4*)&hw[0];
            *(uint4*)&sA[arow][acb + 8] = *(uint4*)&hw[4];
        } else {
            uint4 v0 = make_uint4(0, 0, 0, 0), v1 = make_uint4(0, 0, 0, 0);
            if (arid >= 0) {
                const __half* ap = g_e1h + (size_t)arid * 4096 + k0 + acb;
                v0 = *(const uint4*)(ap);
                v1 = *(const uint4*)(ap + 8);
            }
            *(uint4*)&sA[arow][acb]     = v0;
            *(uint4*)&sA[arow][acb + 8] = v1;
        }
        {
            const float* bp = W + (size_t)(k0 + brow) * N + nBase + bcb;
            float bv[16];
            *(float4*)&bv[0]  = *(const float4*)(bp);
            *(float4*)&bv[4]  = *(const float4*)(bp + 4);
            *(float4*)&bv[8]  = *(const float4*)(bp + 8);
            *(float4*)&bv[12] = *(const float4*)(bp + 12);
            uint32_t hw[8];
            cvt_h16(bv, hw);
            *(uint4*)&sB[brow][bcb]     = *(uint4*)&hw[0];
            *(uint4*)&sB[brow][bcb + 8] = *(uint4*)&hw[4];
        }
        __syncthreads();

#pragma unroll
        for (int chunk = 0; chunk < 2; chunk++) {
            uint32_t Af[4][4], Bf[4][2];
#pragma unroll
            for (int mi = 0; mi < 4; mi++)
                ldsm_x4(Af[mi][0], Af[mi][1], Af[mi][2], Af[mi][3],
                        aBase + mi * (16 * MA_STR * 2) + chunk * 32);
#pragma unroll
            for (int g = 0; g < 2; g++) {
                uint32_t r0, r1, r2, r3;
                ldsm_x4_t(r0, r1, r2, r3, bBase + chunk * (16 * MB_STR * 2) + g * 32);
                Bf[2 * g][0] = r0; Bf[2 * g][1] = r1; Bf[2 * g + 1][0] = r2; Bf[2 * g + 1][1] = r3;
            }
#pragma unroll
            for (int mi = 0; mi < 4; mi++)
#pragma unroll
                for (int ni = 0; ni < 4; ni++)
                    mma_f16(acc[mi][ni], Af[mi], Bf[ni]);
        }
        __syncthreads();
    }

    const int lr = lane >> 2, lc = (lane & 3) * 2;
#pragma unroll
    for (int mi = 0; mi < 4; mi++) {
        int a0 = rows[wmBase + mi * 16 + lr];
        int a1 = rows[wmBase + mi * 16 + lr + 8];
#pragma unroll
        for (int ni = 0; ni < 4; ni++) {
            int col = nBase + wnBase + ni * 8 + lc;
            float b0 = bias[col], b1 = bias[col + 1];
            float v00 = acc[mi][ni][0] + b0, v01 = acc[mi][ni][1] + b1;
            float v10 = acc[mi][ni][2] + b0, v11 = acc[mi][ni][3] + b1;
            if (PHASE == 1) {
                v00 *= sigmoidf_(v00); v01 *= sigmoidf_(v01);
                v10 *= sigmoidf_(v10); v11 *= sigmoidf_(v11);
                if (a0 >= 0) {
                    __half2 p = __floats2half2_rn(v00, v01);
                    *(__half2*)(g_e1h + (size_t)a0 * 4096 + col) = p;
                }
                if (a1 >= 0) {
                    __half2 p = __floats2half2_rn(v10, v11);
                    *(__half2*)(g_e1h + (size_t)a1 * 4096 + col) = p;
                }
            } else {
                float w0 = (a0 >= 0) ? g_w[a0] : 0.f;
                float w1 = (a1 >= 0) ? g_w[a1] : 0.f;
                if (a0 >= 0) *(float2*)(g_e2 + (size_t)a0 * 1024 + col) = make_float2(v00 * w0, v01 * w0);
                if (a1 >= 0) *(float2*)(g_e2 + (size_t)a1 * 1024 + col) = make_float2(v10 * w1, v11 * w1);
            }
        }
    }
}

// ---------------- x -> fp16 hi / scaled-lo ----------------
__global__ void convx_kernel(const float* __restrict__ x) {
    int i = (blockIdx.x * 256 + threadIdx.x) * 4;
    float4 v = *(const float4*)(x + i);
    float a[4] = {v.x, v.y, v.z, v.w};
#pragma unroll
    for (int j = 0; j < 4; j++) {
        __half h = __float2half_rn(a[j]);
        g_xh[i + j] = h;
        g_xl[i + j] = __float2half_rn((a[j] - __half2float(h)) * LO_SCALE);
    }
}

// ---------------- rotary ----------------
__global__ void rotary_kernel(const float* __restrict__ sinp, const float* __restrict__ cosp) {
    int r = blockIdx.x;
    int t = r & (T_ - 1);
    const float* pr = g_P + (size_t)r * 2048;
    float* xr = g_XR + (size_t)r * 1024;
    for (int i = threadIdx.x; i < 512; i += 256) {
        float c = cosp[t * 512 + i], s = sinp[t * 512 + i];
        float a0 = pr[2 * i], a1 = pr[2 * i + 1];
        xr[2 * i]     = a0 * c - a1 * s;
        xr[2 * i + 1] = a0 * s + a1 * c;
    }
}

// ---------------- dwconv + gate + RMS -> glcm ----------------
__global__ void glcm_kernel(const float* __restrict__ Wdw, const float* __restrict__ bdw,
                            const float* __restrict__ gg) {
    int r = blockIdx.x;
    int b = r >> 9, t = r & 511;
    float vals[4];
    float ss = 0.f;
#pragma unroll
    for (int j = 0; j < 4; j++) {
        int d = threadIdx.x + j * 256;
        float conv = bdw[d];
#pragma unroll
        for (int k = 0; k < 7; k++) {
            int tt = t + k - 3;
            if (tt >= 0 && tt < T_)
                conv += g_XR[(size_t)(b * T_ + tt) * 1024 + d] * Wdw[k * 1024 + d];
        }
        float xb = g_P[(size_t)r * 2048 + 1024 + d];
        float v = conv * sigmoidf_(conv) * sigmoidf_(xb);
        vals[j] = v;
        ss += v * v;
    }
    ss = block_sum256(ss);
    float inv = 1.f / sqrtf(ss * (1.f / 1024.f) + EPS_);
#pragma unroll
    for (int j = 0; j < 4; j++) {
        int d = threadIdx.x + j * 256;
        g_glcm[(size_t)r * 1024 + d] = gg[d] * vals[j] * inv;
    }
}

// ---------------- sequential S6 scan, depth-2 prefetch, fp16 y mirrors --------
__global__ void scan_kernel(const float* __restrict__ Alog) {
    int gw = (blockIdx.x * blockDim.x + threadIdx.x) >> 5;
    int lane = threadIdx.x & 31;
    int b = gw >> 9;
    int spair = gw & 511;
    int half = lane >> 4, n = lane & 15;
    int s = spair * 2 + half;
    float A = -expf(Alog[s * 16 + n]);
    float h = 0.f;
    int r = b * T_;

    const float* dp = g_delta + s;
    const float* up = g_XI + s;
    const float* Bp = g_Bmat + s * 16 + n;
    const float* Cp = g_Cmat + s * 16 + n;

    float dv[2], uv[2], Bv[2], Cv[2];
#pragma unroll
    for (int q = 0; q < 2; q++) {
        size_t rq = (size_t)(r + q);
        dv[q] = dp[rq * 1024];
        uv[q] = up[rq * 2048];
        Bv[q] = Bp[rq * 16384];
        Cv[q] = Cp[rq * 16384];
    }

    for (int t = 0; t < T_; t++) {
        const int slot = t & 1;
        float d = dv[slot], u = uv[slot], Bq = Bv[slot], Cq = Cv[slot];
        if (t + 2 < T_) {
            size_t r2 = (size_t)(r + 2);
            dv[slot] = dp[r2 * 1024];
            uv[slot] = up[r2 * 2048];
            Bv[slot] = Bp[r2 * 16384];
            Cv[slot] = Cp[r2 * 16384];
        }
        h = expf(d * A) * h + (d * u) * Bq;
        float p = h * Cq;
        p += __shfl_xor_sync(0xffffffffu, p, 1);
        p += __shfl_xor_sync(0xffffffffu, p, 2);
        p += __shfl_xor_sync(0xffffffffu, p, 4);
        p += __shfl_xor_sync(0xffffffffu, p, 8);
        if (n == 0) {
            size_t idx = (size_t)r * 1024 + s;
            g_y[idx] = p;
            __half hh = __float2half_rn(p);
            g_yh[idx] = hh;
            g_yl[idx] = __float2half_rn((p - __half2float(hh)) * LO_SCALE);
        }
        r++;
    }
}

// ---------------- combine (rms of yo fused in) ----------------
__global__ void combine_kernel(const float* __restrict__ x, const float* __restrict__ gfg,
                               const float* __restrict__ s6g) {
    int r = blockIdx.x;
    const float* yor = g_yo + (size_t)r * 1024;
    float yov[4];
    float ss1 = 0.f;
#pragma unroll
    for (int j = 0; j < 4; j++) {
        int d = threadIdx.x + j * 256;
        float v = yor[d];
        yov[j] = v;
        ss1 += v * v;
    }
    ss1 = block_sum256(ss1);
    float inv1 = 1.f / sqrtf(ss1 * (1.f / 1024.f) + EPS_);

    float vals[4];
    float ss2 = 0.f;
#pragma unroll
    for (int j = 0; j < 4; j++) {
        int d = threadIdx.x + j * 256;
        size_t idx = (size_t)r * 1024 + d;
        float s6 = s6g[d] * yov[j] * inv1;
        float v = g_g1[idx] * s6 + g_g2[idx] * g_glcm[idx];
        vals[j] = v;
        ss2 += v * v;
    }
    ss2 = block_sum256(ss2);
    float inv2 = 1.f / sqrtf(ss2 * (1.f / 1024.f) + EPS_);
#pragma unroll
    for (int j = 0; j < 4; j++) {
        int d = threadIdx.x + j * 256;
        size_t idx = (size_t)r * 1024 + d;
        g_h[idx] = x[idx] + gfg[d] * vals[j] * inv2;
    }
}

// ---------------- MoE routing ----------------
__global__ void zero_cnt_kernel() {
    if (threadIdx.x < E_) g_cnt[threadIdx.x] = 0;
}

__global__ void route_kernel(const float* __restrict__ Wg) {
    int warp = threadIdx.x >> 5, lane = threadIdx.x & 31;
    int token = blockIdx.x * 8 + warp;
    float acc[16];
#pragma unroll
    for (int e = 0; e < 16; e++) acc[e] = 0.f;
    const float* hrow = g_h + (size_t)token * 1024;
    for (int d = lane; d < 1024; d += 32) {
        float xv = hrow[d];
#pragma unroll
        for (int e = 0; e < 16; e++) acc[e] += xv * Wg[d * 16 + e];
    }
#pragma unroll
    for (int e = 0; e < 16; e++) {
#pragma unroll
        for (int o = 16; o; o >>= 1) acc[e] += __shfl_xor_sync(0xffffffffu, acc[e], o);
    }
    if (lane == 0) {
        float v0 = -1e30f; int i0 = 0;
#pragma unroll
        for (int e = 0; e < 16; e++) if (acc[e] > v0) { v0 = acc[e]; i0 = e; }
        float v1 = -1e30f; int i1 = 0;
#pragma unroll
        for (int e = 0; e < 16; e++) if (e != i0 && acc[e] > v1) { v1 = acc[e]; i1 = e; }
        float w0 = 1.f / (1.f + expf(v1 - v0));
        g_w[token * 2]     = w0;
        g_w[token * 2 + 1] = 1.f - w0;
        int p0 = atomicAdd(&g_cnt[i0], 1);
        g_list[i0 * 2048 + p0] = token * 2;
        int p1 = atomicAdd(&g_cnt[i1], 1);
        g_list[i1 * 2048 + p1] = token * 2 + 1;
    }
}

// ---------------- final ----------------
__global__ void final_kernel(float* __restrict__ out) {
    int idx = blockIdx.x * 256 + threadIdx.x;
    int r = idx >> 10, d = idx & 1023;
    out[idx] = g_h[idx] + g_e2[(size_t)r * 2048 + d] + g_e2[(size_t)r * 2048 + 1024 + d];
}

// ---------------- launch ----------------
extern "C" void kernel_launch(void* const* d_in, const int* /*in_sizes*/, int /*n_in*/,
                              void* d_out, int /*out_size*/) {
    const float* x    = (const float*)d_in[0];
    const float* sinp = (const float*)d_in[1];
    const float* cosp = (const float*)d_in[2];
    const float* Wp   = (const float*)d_in[3];
    const float* bp   = (const float*)d_in[4];
    const float* Wdw  = (const float*)d_in[5];
    const float* bdw  = (const float*)d_in[6];
    const float* glg  = (const float*)d_in[7];
    const float* Win  = (const float*)d_in[8];
    const float* bin  = (const float*)d_in[9];
    const float* Wd   = (const float*)d_in[10];
    const float* bd   = (const float*)d_in[11];
    const float* WB   = (const float*)d_in[12];
    const float* bB   = (const float*)d_in[13];
    const float* WC   = (const float*)d_in[14];
    const float* bC   = (const float*)d_in[15];
    const float* Alog = (const float*)d_in[16];
    const float* Wout = (const float*)d_in[17];
    const float* bout = (const float*)d_in[18];
    const float* s6g  = (const float*)d_in[19];
    const float* gfW1 = (const float*)d_in[20];
    const float* gfb1 = (const float*)d_in[21];
    const float* gfW2 = (const float*)d_in[22];
    const float* gfb2 = (const float*)d_in[23];
    const float* gfg  = (const float*)d_in[24];
    const float* Wg   = (const float*)d_in[25];
    const float* mW1  = (const float*)d_in[26];
    const float* mb1  = (const float*)d_in[27];
    const float* mW2  = (const float*)d_in[28];
    const float* mb2  = (const float*)d_in[29];
    float* out = (float*)d_out;

    cudaFuncSetAttribute(wgemm3, cudaFuncAttributeMaxDynamicSharedMemorySize, DSMEM);

    float *pP, *pXI, *pDelta, *pB, *pC, *pYO, *pG1, *pG2;
    cudaGetSymbolAddress((void**)&pP,     g_P);
    cudaGetSymbolAddress((void**)&pXI,    g_XI);
    cudaGetSymbolAddress((void**)&pDelta, g_delta);
    cudaGetSymbolAddress((void**)&pB,     g_Bmat);
    cudaGetSymbolAddress((void**)&pC,     g_Cmat);
    cudaGetSymbolAddress((void**)&pYO,    g_yo);
    cudaGetSymbolAddress((void**)&pG1,    g_g1);
    cudaGetSymbolAddress((void**)&pG2,    g_g2);

    __half *xh, *xl, *XIh, *XIl, *yh, *yl;
    cudaGetSymbolAddress((void**)&xh,  g_xh);  cudaGetSymbolAddress((void**)&xl,  g_xl);
    cudaGetSymbolAddress((void**)&XIh, g_XIh); cudaGetSymbolAddress((void**)&XIl, g_XIl);
    cudaGetSymbolAddress((void**)&yh,  g_yh);  cudaGetSymbolAddress((void**)&yl,  g_yl);

    // 0) x -> fp16 hi / scaled-lo mirror
    convx_kernel<<<1024, 256>>>(x);

    // 1+2) P (z=0) + XI (z=1, emits fp16 mirrors)
    wgemm3<<<dim3(8, 16, 2), 256, DSMEM>>>(
        xh, xl, xh, xl, xh, xl,
        Wp, Win, Win, bp, bin, bin, pP, pXI, pXI,
        2048, 2048, 2048, 0, 0, 0, XIh, XIl, 1024);

    // 3) rotary + glcm
    rotary_kernel<<<BT, 256>>>(sinp, cosp);
    glcm_kernel<<<BT, 256>>>(Wdw, bdw, glg);

    // 5+6+7) B (z=0) + C (z=1) + delta (z=2, softplus)
    wgemm3<<<dim3(8, 128, 3), 256, DSMEM>>>(
        XIh, XIl, XIh, XIl, XIh, XIl,
        WB, WC, Wd, bB, bC, bd, pB, pC, pDelta,
        16384, 16384, 1024, 0, 0, 1, nullptr, nullptr, 2048);

    // 8) scan
    scan_kernel<<<128, 256>>>(Alog);

    // 9+10) g1 (sigmoid) + g2 (sigmoid) + yo (none) in one wave
    wgemm3<<<dim3(8, 8, 3), 256, DSMEM>>>(
        xh, xl, xh, xl, yh, yl,
        gfW1, gfW2, Wout, gfb1, gfb2, bout, pG1, pG2, pYO,
        1024, 1024, 1024, 2, 2, 0, nullptr, nullptr, 1024);

    // 11) combine (rms fused)
    combine_kernel<<<BT, 256>>>(x, gfg, s6g);

    // 12) routing
    zero_cnt_kernel<<<1, 32>>>();
    route_kernel<<<128, 256>>>(Wg);

    // 13/14) expert FFN — single-pass fp16
    moe_fp16_kernel<1><<<dim3(16, 32, 16), 256>>>(mW1, mb1);
    moe_fp16_kernel<2><<<dim3(16, 8, 16), 256>>>(mW2, mb2);

    // 15) final
    final_kernel<<<4096, 256>>>(out);
}

// round 17
// speedup vs baseline: 1.4179x; 1.4179x over previous
#include <cuda_runtime.h>
#include <cuda_bf16.h>
#include <cuda_fp16.h>
#include <math.h>
#include <stdint.h>

// ---------------- constants ----------------
constexpr int E_  = 16;
constexpr int T_  = 512;
constexpr int BT  = 1024;   // B*T
constexpr float EPS_ = 1e-8f;

// ---------------- f32 scratch ----------------
__device__ float g_P    [BT * 2048];
__device__ float g_XI   [BT * 2048];
__device__ float g_XR   [BT * 1024];
__device__ float g_glcm [BT * 1024];
__device__ float g_delta[BT * 1024];
__device__ float g_Bmat [BT * 16384];
__device__ float g_Cmat [BT * 16384];
__device__ float g_y    [BT * 1024];
__device__ float g_yo   [BT * 1024];
__device__ float g_g1   [BT * 1024];
__device__ float g_g2   [BT * 1024];
__device__ float g_h    [BT * 1024];
__device__ float g_e2   [2 * BT * 1024];
__device__ int   g_cnt  [E_];
__device__ int   g_list [E_ * 2048];
__device__ float g_w    [2 * BT];

// ---------------- fp16 MoE intermediate ----------------
__device__ __half g_e1h [2 * BT * 4096];

// ---------------- bf16 hi/lo activation mirrors (dense path) ----------------
__device__ __nv_bfloat16 g_xh [BT * 1024], g_xl [BT * 1024];
__device__ __nv_bfloat16 g_XIh[BT * 2048], g_XIl[BT * 2048];
__device__ __nv_bfloat16 g_yh [BT * 1024], g_yl [BT * 1024];

// ---------------- helpers ----------------
__device__ __forceinline__ float sigmoidf_(float x) { return 1.f / (1.f + expf(-x)); }

// safe for repeated use within one kernel (leading barrier protects sh[] reuse)
__device__ __forceinline__ float block_sum256(float v) {
    __shared__ float sh[8];
    int lane = threadIdx.x & 31, w = threadIdx.x >> 5;
    __syncthreads();
#pragma unroll
    for (int o = 16; o; o >>= 1) v += __shfl_xor_sync(0xffffffffu, v, o);
    if (lane == 0) sh[w] = v;
    __syncthreads();
    float s = 0.f;
#pragma unroll
    for (int i = 0; i < 8; i++) s += sh[i];
    return s;
}

__device__ __forceinline__ uint32_t smem_u32(const void* p) {
    return (uint32_t)__cvta_generic_to_shared(p);
}

__device__ __forceinline__ void ldsm_x4(uint32_t& r0, uint32_t& r1, uint32_t& r2, uint32_t& r3, uint32_t addr) {
    asm volatile("ldmatrix.sync.aligned.m8n8.x4.shared.b16 {%0,%1,%2,%3}, [%4];"
        : "=r"(r0), "=r"(r1), "=r"(r2), "=r"(r3) : "r"(addr));
}
__device__ __forceinline__ void ldsm_x4_t(uint32_t& r0, uint32_t& r1, uint32_t& r2, uint32_t& r3, uint32_t addr) {
    asm volatile("ldmatrix.sync.aligned.m8n8.x4.trans.shared.b16 {%0,%1,%2,%3}, [%4];"
        : "=r"(r0), "=r"(r1), "=r"(r2), "=r"(r3) : "r"(addr));
}
__device__ __forceinline__ void mma_bf16(float* c, const uint32_t* a, const uint32_t* b) {
    asm volatile("mma.sync.aligned.m16n8k16.row.col.f32.bf16.bf16.f32 "
        "{%0,%1,%2,%3}, {%4,%5,%6,%7}, {%8,%9}, {%0,%1,%2,%3};"
        : "+f"(c[0]), "+f"(c[1]), "+f"(c[2]), "+f"(c[3])
        : "r"(a[0]), "r"(a[1]), "r"(a[2]), "r"(a[3]), "r"(b[0]), "r"(b[1]));
}
__device__ __forceinline__ void mma_f16(float* c, const uint32_t* a, const uint32_t* b) {
    asm volatile("mma.sync.aligned.m16n8k16.row.col.f32.f16.f16.f32 "
        "{%0,%1,%2,%3}, {%4,%5,%6,%7}, {%8,%9}, {%0,%1,%2,%3};"
        : "+f"(c[0]), "+f"(c[1]), "+f"(c[2]), "+f"(c[3])
        : "r"(a[0]), "r"(a[1]), "r"(a[2]), "r"(a[3]), "r"(b[0]), "r"(b[1]));
}
__device__ __forceinline__ void cvt_split16(const float* v, uint32_t* hi, uint32_t* lo) {
#pragma unroll
    for (int i = 0; i < 8; i++) {
        float x0 = v[2 * i], x1 = v[2 * i + 1];
        __nv_bfloat16 h0 = __float2bfloat16(x0), h1 = __float2bfloat16(x1);
        float r0 = x0 - __bfloat162float(h0), r1 = x1 - __bfloat162float(h1);
        __nv_bfloat16 l0 = __float2bfloat16(r0), l1 = __float2bfloat16(r1);
        hi[i] = ((uint32_t)__bfloat16_as_ushort(h1) << 16) | __bfloat16_as_ushort(h0);
        lo[i] = ((uint32_t)__bfloat16_as_ushort(l1) << 16) | __bfloat16_as_ushort(l0);
    }
}
__device__ __forceinline__ void cvt_h16(const float* v, uint32_t* h) {
#pragma unroll
    for (int i = 0; i < 8; i++) {
        __half2 p = __floats2half2_rn(v[2 * i], v[2 * i + 1]);
        h[i] = *(uint32_t*)&p;
    }
}

__device__ __forceinline__ void cp16(uint32_t dst, const void* src) {
    asm volatile("cp.async.cg.shared.global [%0], [%1], 16;" :: "r"(dst), "l"(src));
}
#define CP_COMMIT() asm volatile("cp.async.commit_group;" ::: "memory")
#define CP_WAIT1()  asm volatile("cp.async.wait_group 1;" ::: "memory")

// ============================================================================
// Dense GEMM, 3-way z-merged (R14-verified): bf16 hi/lo 3-pass, f32 accum.
// ============================================================================
constexpr int AP = 10240;
constexpr int BP = 8704;
constexpr int STG = 2 * AP + 2 * BP;
constexpr int DSMEM = 2 * STG;

__global__ __launch_bounds__(256)
void wgemm3(const __nv_bfloat16* __restrict__ A0h, const __nv_bfloat16* __restrict__ A0l,
            const __nv_bfloat16* __restrict__ A1h, const __nv_bfloat16* __restrict__ A1l,
            const __nv_bfloat16* __restrict__ A2h, const __nv_bfloat16* __restrict__ A2l,
            const float* __restrict__ W0, const float* __restrict__ W1, const float* __restrict__ W2,
            const float* __restrict__ b0, const float* __restrict__ b1, const float* __restrict__ b2,
            float* __restrict__ C0, float* __restrict__ C1, float* __restrict__ C2,
            int N0, int N1, int N2, int e0, int e1, int e2,
            __nv_bfloat16* __restrict__ Ch, __nv_bfloat16* __restrict__ Cl,
            int K) {
    extern __shared__ char smem[];
    const uint32_t sb = smem_u32(smem);

    const int z = blockIdx.z;
    const __nv_bfloat16* __restrict__ Ah = (z == 0) ? A0h : (z == 1) ? A1h : A2h;
    const __nv_bfloat16* __restrict__ Al = (z == 0) ? A0l : (z == 1) ? A1l : A2l;
    const float* __restrict__ W    = (z == 0) ? W0 : (z == 1) ? W1 : W2;
    const float* __restrict__ bias = (z == 0) ? b0 : (z == 1) ? b1 : b2;
    float* __restrict__ C          = (z == 0) ? C0 : (z == 1) ? C1 : C2;
    const int Ntot = (z == 0) ? N0 : (z == 1) ? N1 : N2;
    const int EPI  = (z == 0) ? e0 : (z == 1) ? e1 : e2;
    const bool bout = (Ch != nullptr) && (z == 1);

    const int nBase = blockIdx.y * 128;
    if (nBase >= Ntot) return;   // inactive tile (merged small-N member)

    const int tid = threadIdx.x;
    const int warp = tid >> 5, lane = tid & 31;
    const int wm = warp & 1, wn = warp >> 1;
    const int mBase = blockIdx.x * 128;
    const int wmBase = wm * 64, wnBase = wn * 32;

    const int S = K >> 5;

    auto load_A = [&](int s, int b) {
        const int k0 = s << 5;
        const uint32_t base = sb + b * STG;
#pragma unroll
        for (int i = 0; i < 2; i++) {
            int c = i * 256 + tid;
            int r = c >> 2, c4 = c & 3;
            uint32_t dst = base + (uint32_t)(r * 80 + c4 * 16);
            cp16(dst,      Ah + (size_t)(mBase + r) * K + k0 + c4 * 8);
            cp16(dst + AP, Al + (size_t)(mBase + r) * K + k0 + c4 * 8);
        }
    };

    const int wr = tid >> 3, wc = (tid & 7) * 16;
    float wreg[16];
    auto ldg_W = [&](int s) {
        const float* src = W + (size_t)((s << 5) + wr) * Ntot + nBase + wc;
        *(float4*)&wreg[0]  = *(const float4*)(src);
        *(float4*)&wreg[4]  = *(const float4*)(src + 4);
        *(float4*)&wreg[8]  = *(const float4*)(src + 8);
        *(float4*)&wreg[12] = *(const float4*)(src + 12);
    };
    auto sts_W = [&](int b) {
        uint32_t hi[8], lo[8];
        cvt_split16(wreg, hi, lo);
        const uint32_t off = b * STG + 2 * AP + (uint32_t)(wr * 272 + wc * 2);
        *(uint4*)(smem + off)           = *(uint4*)&hi[0];
        *(uint4*)(smem + off + 16)      = *(uint4*)&hi[4];
        *(uint4*)(smem + off + BP)      = *(uint4*)&lo[0];
        *(uint4*)(smem + off + BP + 16) = *(uint4*)&lo[4];
    };

    float acc[4][4][4] = {};

    const int lrow = lane & 15;
    const int lcolB = ((lane >> 4) << 3) * 2;

    ldg_W(0);
    load_A(0, 0); CP_COMMIT();
    load_A(1, 1); CP_COMMIT();

    for (int s = 0; s < S; s++) {
        const int b = s & 1;
        sts_W(b);
        if (s + 1 < S) ldg_W(s + 1);
        CP_WAIT1();
        __syncthreads();

        const uint32_t base = sb + b * STG;
        const uint32_t aH = base + (uint32_t)((wmBase + lrow) * 80) + lcolB;
        const uint32_t aL = aH + AP;
        const uint32_t bH = base + 2 * AP + (uint32_t)(lrow * 272) + (uint32_t)(wnBase * 2) + lcolB;
        const uint32_t bL = bH + BP;

#pragma unroll
        for (int chunk = 0; chunk < 2; chunk++) {
            uint32_t Afh[4][4], Afl[4][4], Bfh[4][2], Bfl[4][2];
#pragma unroll
            for (int mi = 0; mi < 4; mi++) {
                ldsm_x4(Afh[mi][0], Afh[mi][1], Afh[mi][2], Afh[mi][3],
                        aH + mi * (16 * 80) + chunk * 32);
                ldsm_x4(Afl[mi][0], Afl[mi][1], Afl[mi][2], Afl[mi][3],
                        aL + mi * (16 * 80) + chunk * 32);
            }
#pragma unroll
            for (int g = 0; g < 2; g++) {
                uint32_t r0, r1, r2, r3;
                ldsm_x4_t(r0, r1, r2, r3, bH + chunk * (16 * 272) + g * 32);
                Bfh[2 * g][0] = r0; Bfh[2 * g][1] = r1; Bfh[2 * g + 1][0] = r2; Bfh[2 * g + 1][1] = r3;
                ldsm_x4_t(r0, r1, r2, r3, bL + chunk * (16 * 272) + g * 32);
                Bfl[2 * g][0] = r0; Bfl[2 * g][1] = r1; Bfl[2 * g + 1][0] = r2; Bfl[2 * g + 1][1] = r3;
            }
#pragma unroll
            for (int mi = 0; mi < 4; mi++)
#pragma unroll
                for (int ni = 0; ni < 4; ni++) {
                    mma_bf16(acc[mi][ni], Afh[mi], Bfh[ni]);
                    mma_bf16(acc[mi][ni], Afh[mi], Bfl[ni]);
                    mma_bf16(acc[mi][ni], Afl[mi], Bfh[ni]);
                }
        }
        __syncthreads();
        if (s + 2 < S) load_A(s + 2, b);
        CP_COMMIT();
    }

    const int lr = lane >> 2, lc = (lane & 3) * 2;
#pragma unroll
    for (int mi = 0; mi < 4; mi++) {
        size_t row0 = (size_t)(mBase + wmBase + mi * 16 + lr);
#pragma unroll
        for (int ni = 0; ni < 4; ni++) {
            int col = nBase + wnBase + ni * 8 + lc;
            float bb0 = bias[col], bb1 = bias[col + 1];
            float v[4] = {acc[mi][ni][0] + bb0, acc[mi][ni][1] + bb1,
                          acc[mi][ni][2] + bb0, acc[mi][ni][3] + bb1};
            if (EPI == 1) {
#pragma unroll
                for (int q = 0; q < 4; q++)
                    v[q] = fmaxf(v[q], 0.f) + log1pf(expf(-fabsf(v[q])));
            } else if (EPI == 2) {
#pragma unroll
                for (int q = 0; q < 4; q++) v[q] = sigmoidf_(v[q]);
            }
            size_t i0 = row0 * Ntot + col;
            size_t i1 = (row0 + 8) * Ntot + col;
            *(float2*)(C + i0) = make_float2(v[0], v[1]);
            *(float2*)(C + i1) = make_float2(v[2], v[3]);
            if (bout) {
                __nv_bfloat16 h0 = __float2bfloat16(v[0]), h1 = __float2bfloat16(v[1]);
                __nv_bfloat16 h2 = __float2bfloat16(v[2]), h3 = __float2bfloat16(v[3]);
                Ch[i0] = h0; Ch[i0 + 1] = h1; Ch[i1] = h2; Ch[i1 + 1] = h3;
                Cl[i0]     = __float2bfloat16(v[0] - __bfloat162float(h0));
                Cl[i0 + 1] = __float2bfloat16(v[1] - __bfloat162float(h1));
                Cl[i1]     = __float2bfloat16(v[2] - __bfloat162float(h2));
                Cl[i1 + 1] = __float2bfloat16(v[3] - __bfloat162float(h3));
            }
        }
    }
}

// ============================================================================
// MoE gather-GEMM, single-pass fp16 (verified R12)
// ============================================================================
constexpr int MA_STR = 40;
constexpr int MB_STR = 136;

template <int PHASE>
__global__ __launch_bounds__(256)
void moe_fp16_kernel(const float* __restrict__ Wall, const float* __restrict__ ball) {
    constexpr int K = (PHASE == 1) ? 1024 : 4096;
    constexpr int N = (PHASE == 1) ? 4096 : 1024;
    const int e = blockIdx.z;
    const int mc = g_cnt[e];
    const int m0 = blockIdx.x * 128;
    if (m0 >= mc) return;
    const float* W = Wall + (size_t)e * K * N;
    const float* bias = ball + (size_t)e * N;

    __shared__ int rows[128];
    __shared__ __half sA[128][MA_STR];
    __shared__ __half sB[32][MB_STR];

    const int tid = threadIdx.x;
    const int warp = tid >> 5, lane = tid & 31;
    const int wm = warp & 1, wn = warp >> 1;
    const int nBase = blockIdx.y * 128;
    const int wmBase = wm * 64, wnBase = wn * 32;

    if (tid < 128) {
        int m = m0 + tid;
        rows[tid] = (m < mc) ? g_list[e * 2048 + m] : -1;
    }
    __syncthreads();

    const int arow = tid >> 1, acb = (tid & 1) * 16;
    const int brow = tid >> 3, bcb = (tid & 7) * 16;
    const int arid = rows[arow];

    const int lrow = lane & 15;
    const int lcol = (lane >> 4) << 3;
    const uint32_t aBase = smem_u32(&sA[wmBase + lrow][lcol]);
    const uint32_t bBase = smem_u32(&sB[lrow][wnBase + lcol]);

    float acc[4][4][4] = {};

    for (int k0 = 0; k0 < K; k0 += 32) {
        if (PHASE == 1) {
            float av[16];
            if (arid >= 0) {
                const float* ap = g_h + (size_t)(arid >> 1) * 1024 + k0 + acb;
                *(float4*)&av[0]  = *(const float4*)(ap);
                *(float4*)&av[4]  = *(const float4*)(ap + 4);
                *(float4*)&av[8]  = *(const float4*)(ap + 8);
                *(float4*)&av[12] = *(const float4*)(ap + 12);
            } else {
#pragma unroll
                for (int i = 0; i < 16; i++) av[i] = 0.f;
            }
            uint32_t hw[8];
            cvt_h16(av, hw);
            *(uint4*)&sA[arow][acb]     = *(uint4*)&hw[0];
            *(uint4*)&sA[arow][acb + 8] = *(uint4*)&hw[4];
        } else {
            uint4 v0 = make_uint4(0, 0, 0, 0), v1 = make_uint4(0, 0, 0, 0);
            if (arid >= 0) {
                const __half* ap = g_e1h + (size_t)arid * 4096 + k0 + acb;
                v0 = *(const uint4*)(ap);
                v1 = *(const uint4*)(ap + 8);
            }
            *(uint4*)&sA[arow][acb]     = v0;
            *(uint4*)&sA[arow][acb + 8] = v1;
        }
        {
            const float* bp = W + (size_t)(k0 + brow) * N + nBase + bcb;
            float bv[16];
            *(float4*)&bv[0]  = *(const float4*)(bp);
            *(float4*)&bv[4]  = *(const float4*)(bp + 4);
            *(float4*)&bv[8]  = *(const float4*)(bp + 8);
            *(float4*)&bv[12] = *(const float4*)(bp + 12);
            uint32_t hw[8];
            cvt_h16(bv, hw);
            *(uint4*)&sB[brow][bcb]     = *(uint4*)&hw[0];
            *(uint4*)&sB[brow][bcb + 8] = *(uint4*)&hw[4];
        }
        __syncthreads();

#pragma unroll
        for (int chunk = 0; chunk < 2; chunk++) {
            uint32_t Af[4][4], Bf[4][2];
#pragma unroll
            for (int mi = 0; mi < 4; mi++)
                ldsm_x4(Af[mi][0], Af[mi][1], Af[mi][2], Af[mi][3],
                        aBase + mi * (16 * MA_STR * 2) + chunk * 32);
#pragma unroll
            for (int g = 0; g < 2; g++) {
                uint32_t r0, r1, r2, r3;
                ldsm_x4_t(r0, r1, r2, r3, bBase + chunk * (16 * MB_STR * 2) + g * 32);
                Bf[2 * g][0] = r0; Bf[2 * g][1] = r1; Bf[2 * g + 1][0] = r2; Bf[2 * g + 1][1] = r3;
            }
#pragma unroll
            for (int mi = 0; mi < 4; mi++)
#pragma unroll
                for (int ni = 0; ni < 4; ni++)
                    mma_f16(acc[mi][ni], Af[mi], Bf[ni]);
        }
        __syncthreads();
    }

    const int lr = lane >> 2, lc = (lane & 3) * 2;
#pragma unroll
    for (int mi = 0; mi < 4; mi++) {
        int a0 = rows[wmBase + mi * 16 + lr];
        int a1 = rows[wmBase + mi * 16 + lr + 8];
#pragma unroll
        for (int ni = 0; ni < 4; ni++) {
            int col = nBase + wnBase + ni * 8 + lc;
            float b0 = bias[col], b1 = bias[col + 1];
            float v00 = acc[mi][ni][0] + b0, v01 = acc[mi][ni][1] + b1;
            float v10 = acc[mi][ni][2] + b0, v11 = acc[mi][ni][3] + b1;
            if (PHASE == 1) {
                v00 *= sigmoidf_(v00); v01 *= sigmoidf_(v01);
                v10 *= sigmoidf_(v10); v11 *= sigmoidf_(v11);
                if (a0 >= 0) {
                    __half2 p = __floats2half2_rn(v00, v01);
                    *(__half2*)(g_e1h + (size_t)a0 * 4096 + col) = p;
                }
                if (a1 >= 0) {
                    __half2 p = __floats2half2_rn(v10, v11);
                    *(__half2*)(g_e1h + (size_t)a1 * 4096 + col) = p;
                }
            } else {
                float w0 = (a0 >= 0) ? g_w[a0] : 0.f;
                float w1 = (a1 >= 0) ? g_w[a1] : 0.f;
                if (a0 >= 0) *(float2*)(g_e2 + (size_t)a0 * 1024 + col) = make_float2(v00 * w0, v01 * w0);
                if (a1 >= 0) *(float2*)(g_e2 + (size_t)a1 * 1024 + col) = make_float2(v10 * w1, v11 * w1);
            }
        }
    }
}

// ---------------- x -> bf16 hi/lo ----------------
__global__ void convx_kernel(const float* __restrict__ x) {
    int i = (blockIdx.x * 256 + threadIdx.x) * 4;
    float4 v = *(const float4*)(x + i);
    float a[4] = {v.x, v.y, v.z, v.w};
#pragma unroll
    for (int j = 0; j < 4; j++) {
        __nv_bfloat16 h = __float2bfloat16(a[j]);
        g_xh[i + j] = h;
        g_xl[i + j] = __float2bfloat16(a[j] - __bfloat162float(h));
    }
}

// ---------------- rotary ----------------
__global__ void rotary_kernel(const float* __restrict__ sinp, const float* __restrict__ cosp) {
    int r = blockIdx.x;
    int t = r & (T_ - 1);
    const float* pr = g_P + (size_t)r * 2048;
    float* xr = g_XR + (size_t)r * 1024;
    for (int i = threadIdx.x; i < 512; i += 256) {
        float c = cosp[t * 512 + i], s = sinp[t * 512 + i];
        float a0 = pr[2 * i], a1 = pr[2 * i + 1];
        xr[2 * i]     = a0 * c - a1 * s;
        xr[2 * i + 1] = a0 * s + a1 * c;
    }
}

// ---------------- dwconv + gate + RMS -> glcm ----------------
__global__ void glcm_kernel(const float* __restrict__ Wdw, const float* __restrict__ bdw,
                            const float* __restrict__ gg) {
    int r = blockIdx.x;
    int b = r >> 9, t = r & 511;
    float vals[4];
    float ss = 0.f;
#pragma unroll
    for (int j = 0; j < 4; j++) {
        int d = threadIdx.x + j * 256;
        float conv = bdw[d];
#pragma unroll
        for (int k = 0; k < 7; k++) {
            int tt = t + k - 3;
            if (tt >= 0 && tt < T_)
                conv += g_XR[(size_t)(b * T_ + tt) * 1024 + d] * Wdw[k * 1024 + d];
        }
        float xb = g_P[(size_t)r * 2048 + 1024 + d];
        float v = conv * sigmoidf_(conv) * sigmoidf_(xb);
        vals[j] = v;
        ss += v * v;
    }
    ss = block_sum256(ss);
    float inv = 1.f / sqrtf(ss * (1.f / 1024.f) + EPS_);
#pragma unroll
    for (int j = 0; j < 4; j++) {
        int d = threadIdx.x + j * 256;
        g_glcm[(size_t)r * 1024 + d] = gg[d] * vals[j] * inv;
    }
}

// ---------------- sequential S6 scan, depth-2 prefetch, bf16 y mirrors -------
__global__ void scan_kernel(const float* __restrict__ Alog) {
    int gw = (blockIdx.x * blockDim.x + threadIdx.x) >> 5;
    int lane = threadIdx.x & 31;
    int b = gw >> 9;
    int spair = gw & 511;
    int half = lane >> 4, n = lane & 15;
    int s = spair * 2 + half;
    float A = -expf(Alog[s * 16 + n]);
    float h = 0.f;
    int r = b * T_;

    const float* dp = g_delta + s;
    const float* up = g_XI + s;
    const float* Bp = g_Bmat + s * 16 + n;
    const float* Cp = g_Cmat + s * 16 + n;

    float dv[2], uv[2], Bv[2], Cv[2];
#pragma unroll
    for (int q = 0; q < 2; q++) {
        size_t rq = (size_t)(r + q);
        dv[q] = dp[rq * 1024];
        uv[q] = up[rq * 2048];
        Bv[q] = Bp[rq * 16384];
        Cv[q] = Cp[rq * 16384];
    }

    for (int t = 0; t < T_; t++) {
        const int slot = t & 1;
        float d = dv[slot], u = uv[slot], Bq = Bv[slot], Cq = Cv[slot];
        if (t + 2 < T_) {
            size_t r2 = (size_t)(r + 2);
            dv[slot] = dp[r2 * 1024];
            uv[slot] = up[r2 * 2048];
            Bv[slot] = Bp[r2 * 16384];
            Cv[slot] = Cp[r2 * 16384];
        }
        h = expf(d * A) * h + (d * u) * Bq;
        float p = h * Cq;
        p += __shfl_xor_sync(0xffffffffu, p, 1);
        p += __shfl_xor_sync(0xffffffffu, p, 2);
        p += __shfl_xor_sync(0xffffffffu, p, 4);
        p += __shfl_xor_sync(0xffffffffu, p, 8);
        if (n == 0) {
            size_t idx = (size_t)r * 1024 + s;
            g_y[idx] = p;
            __nv_bfloat16 hh = __float2bfloat16(p);
            g_yh[idx] = hh;
            g_yl[idx] = __float2bfloat16(p - __bfloat162float(hh));
        }
        r++;
    }
}

// ---------------- combine (rms of yo fused in) ----------------
__global__ void combine_kernel(const float* __restrict__ x, const float* __restrict__ gfg,
                               const float* __restrict__ s6g) {
    int r = blockIdx.x;
    const float* yor = g_yo + (size_t)r * 1024;
    float yov[4];
    float ss1 = 0.f;
#pragma unroll
    for (int j = 0; j < 4; j++) {
        int d = threadIdx.x + j * 256;
        float v = yor[d];
        yov[j] = v;
        ss1 += v * v;
    }
    ss1 = block_sum256(ss1);
    float inv1 = 1.f / sqrtf(ss1 * (1.f / 1024.f) + EPS_);

    float vals[4];
    float ss2 = 0.f;
#pragma unroll
    for (int j = 0; j < 4; j++) {
        int d = threadIdx.x + j * 256;
        size_t idx = (size_t)r * 1024 + d;
        float s6 = s6g[d] * yov[j] * inv1;
        float v = g_g1[idx] * s6 + g_g2[idx] * g_glcm[idx];
        vals[j] = v;
        ss2 += v * v;
    }
    ss2 = block_sum256(ss2);
    float inv2 = 1.f / sqrtf(ss2 * (1.f / 1024.f) + EPS_);
#pragma unroll
    for (int j = 0; j < 4; j++) {
        int d = threadIdx.x + j * 256;
        size_t idx = (size_t)r * 1024 + d;
        g_h[idx] = x[idx] + gfg[d] * vals[j] * inv2;
    }
}

// ---------------- MoE routing ----------------
__global__ void zero_cnt_kernel() {
    if (threadIdx.x < E_) g_cnt[threadIdx.x] = 0;
}

__global__ void route_kernel(const float* __restrict__ Wg) {
    int warp = threadIdx.x >> 5, lane = threadIdx.x & 31;
    int token = blockIdx.x * 8 + warp;
    float acc[16];
#pragma unroll
    for (int e = 0; e < 16; e++) acc[e] = 0.f;
    const float* hrow = g_h + (size_t)token * 1024;
    for (int d = lane; d < 1024; d += 32) {
        float xv = hrow[d];
#pragma unroll
        for (int e = 0; e < 16; e++) acc[e] += xv * Wg[d * 16 + e];
    }
#pragma unroll
    for (int e = 0; e < 16; e++) {
#pragma unroll
        for (int o = 16; o; o >>= 1) acc[e] += __shfl_xor_sync(0xffffffffu, acc[e], o);
    }
    if (lane == 0) {
        float v0 = -1e30f; int i0 = 0;
#pragma unroll
        for (int e = 0; e < 16; e++) if (acc[e] > v0) { v0 = acc[e]; i0 = e; }
        float v1 = -1e30f; int i1 = 0;
#pragma unroll
        for (int e = 0; e < 16; e++) if (e != i0 && acc[e] > v1) { v1 = acc[e]; i1 = e; }
        float w0 = 1.f / (1.f + expf(v1 - v0));
        g_w[token * 2]     = w0;
        g_w[token * 2 + 1] = 1.f - w0;
        int p0 = atomicAdd(&g_cnt[i0], 1);
        g_list[i0 * 2048 + p0] = token * 2;
        int p1 = atomicAdd(&g_cnt[i1], 1);
        g_list[i1 * 2048 + p1] = token * 2 + 1;
    }
}

// ---------------- final ----------------
__global__ void final_kernel(float* __restrict__ out) {
    int idx = blockIdx.x * 256 + threadIdx.x;
    int r = idx >> 10, d = idx & 1023;
    out[idx] = g_h[idx] + g_e2[(size_t)r * 2048 + d] + g_e2[(size_t)r * 2048 + 1024 + d];
}

// ---------------- launch ----------------
extern "C" void kernel_launch(void* const* d_in, const int* /*in_sizes*/, int /*n_in*/,
                              void* d_out, int /*out_size*/) {
    const float* x    = (const float*)d_in[0];
    const float* sinp = (const float*)d_in[1];
    const float* cosp = (const float*)d_in[2];
    const float* Wp   = (const float*)d_in[3];
    const float* bp   = (const float*)d_in[4];
    const float* Wdw  = (const float*)d_in[5];
    const float* bdw  = (const float*)d_in[6];
    const float* glg  = (const float*)d_in[7];
    const float* Win  = (const float*)d_in[8];
    const float* bin  = (const float*)d_in[9];
    const float* Wd   = (const float*)d_in[10];
    const float* bd   = (const float*)d_in[11];
    const float* WB   = (const float*)d_in[12];
    const float* bB   = (const float*)d_in[13];
    const float* WC   = (const float*)d_in[14];
    const float* bC   = (const float*)d_in[15];
    const float* Alog = (const float*)d_in[16];
    const float* Wout = (const float*)d_in[17];
    const float* bout = (const float*)d_in[18];
    const float* s6g  = (const float*)d_in[19];
    const float* gfW1 = (const float*)d_in[20];
    const float* gfb1 = (const float*)d_in[21];
    const float* gfW2 = (const float*)d_in[22];
    const float* gfb2 = (const float*)d_in[23];
    const float* gfg  = (const float*)d_in[24];
    const float* Wg   = (const float*)d_in[25];
    const float* mW1  = (const float*)d_in[26];
    const float* mb1  = (const float*)d_in[27];
    const float* mW2  = (const float*)d_in[28];
    const float* mb2  = (const float*)d_in[29];
    float* out = (float*)d_out;

    cudaFuncSetAttribute(wgemm3, cudaFuncAttributeMaxDynamicSharedMemorySize, DSMEM);

    float *pP, *pXI, *pDelta, *pB, *pC, *pYO, *pG1, *pG2;
    cudaGetSymbolAddress((void**)&pP,     g_P);
    cudaGetSymbolAddress((void**)&pXI,    g_XI);
    cudaGetSymbolAddress((void**)&pDelta, g_delta);
    cudaGetSymbolAddress((void**)&pB,     g_Bmat);
    cudaGetSymbolAddress((void**)&pC,     g_Cmat);
    cudaGetSymbolAddress((void**)&pYO,    g_yo);
    cudaGetSymbolAddress((void**)&pG1,    g_g1);
    cudaGetSymbolAddress((void**)&pG2,    g_g2);

    __nv_bfloat16 *xh, *xl, *XIh, *XIl, *yh, *yl;
    cudaGetSymbolAddress((void**)&xh,  g_xh);  cudaGetSymbolAddress((void**)&xl,  g_xl);
    cudaGetSymbolAddress((void**)&XIh, g_XIh); cudaGetSymbolAddress((void**)&XIl, g_XIl);
    cudaGetSymbolAddress((void**)&yh,  g_yh);  cudaGetSymbolAddress((void**)&yl,  g_yl);

    // 0) x -> bf16 hi/lo mirror
    convx_kernel<<<1024, 256>>>(x);

    // 1+2) P (z=0) + XI (z=1, emits bf16 mirrors)
    wgemm3<<<dim3(8, 16, 2), 256, DSMEM>>>(
        xh, xl, xh, xl, xh, xl,
        Wp, Win, Win, bp, bin, bin, pP, pXI, pXI,
        2048, 2048, 2048, 0, 0, 0, XIh, XIl, 1024);

    // 3) rotary + glcm
    rotary_kernel<<<BT, 256>>>(sinp, cosp);
    glcm_kernel<<<BT, 256>>>(Wdw, bdw, glg);

    // 5+6+7) B (z=0) + C (z=1) + delta (z=2, softplus)
    wgemm3<<<dim3(8, 128, 3), 256, DSMEM>>>(
        XIh, XIl, XIh, XIl, XIh, XIl,
        WB, WC, Wd, bB, bC, bd, pB, pC, pDelta,
        16384, 16384, 1024, 0, 0, 1, nullptr, nullptr, 2048);

    // 8) scan
    scan_kernel<<<128, 256>>>(Alog);

    // 9+10) g1 (sigmoid) + g2 (sigmoid) + yo (none) in one wave
    wgemm3<<<dim3(8, 8, 3), 256, DSMEM>>>(
        xh, xl, xh, xl, yh, yl,
        gfW1, gfW2, Wout, gfb1, gfb2, bout, pG1, pG2, pYO,
        1024, 1024, 1024, 2, 2, 0, nullptr, nullptr, 1024);

    // 11) combine (rms fused)
    combine_kernel<<<BT, 256>>>(x, gfg, s6g);

    // 12) routing
    zero_cnt_kernel<<<1, 32>>>();
    route_kernel<<<128, 256>>>(Wg);

    // 13/14) expert FFN — single-pass fp16
    moe_fp16_kernel<1><<<dim3(16, 32, 16), 256>>>(mW1, mb1);
    moe_fp16_kernel<2><<<dim3(16, 8, 16), 256>>>(mW2, mb2);

    // 15) final
    final_kernel<<<4096, 256>>>(out);
}